// round 16
// baseline (speedup 1.0000x reference)
#include <cuda_runtime.h>
#include <cuda_bf16.h>
#include <math.h>
#include <stdint.h>

#define Bb   16
#define Ll   256
#define Dd   768
#define Hh   12
#define HDd  64
#define NLl  4
#define Ff   3072
#define Ee   50
#define Cc   2
#define ROWS (Bb * Ll)
#define WTOT (16 * Dd * Dd + 8 * Dd * Ff)

// ---------------------------------------------------------------------------
// Scratch (device globals; no allocations allowed)
// ---------------------------------------------------------------------------
__device__ float g_h [ROWS * Dd];
__device__ float g_q [ROWS * Dd];
__device__ float g_k [ROWS * Dd];
__device__ float g_v [ROWS * Dd];
__device__ float g_t [ROWS * Dd];
__device__ float g_qe[ROWS * Hh * Ee];
__device__ __nv_bfloat16 g_hh [ROWS * Dd], g_hl [ROWS * Dd];
__device__ __nv_bfloat16 g_aoh[ROWS * Dd], g_aol[ROWS * Dd];
__device__ __nv_bfloat16 g_ffh[ROWS * Ff], g_ffl[ROWS * Ff];
__device__ __nv_bfloat16 g_wth[WTOT],      g_wtl[WTOT];

__device__ __forceinline__ void split1(float x, __nv_bfloat16& hi, __nv_bfloat16& lo) {
    hi = __float2bfloat16(x);
    lo = __float2bfloat16(x - __bfloat162float(hi));
}

// ---------------------------------------------------------------------------
// PTX helpers (mma.sync path only — tcgen05 unavailable at compute_103 PTX)
// ---------------------------------------------------------------------------
__device__ __forceinline__ void ldsm_x4(uint32_t* r, uint32_t a) {
    asm volatile("ldmatrix.sync.aligned.m8n8.x4.shared.b16 {%0,%1,%2,%3}, [%4];"
                 : "=r"(r[0]), "=r"(r[1]), "=r"(r[2]), "=r"(r[3]) : "r"(a));
}
__device__ __forceinline__ void cpasync16(uint32_t dst, const void* src) {
    asm volatile("cp.async.cg.shared.global [%0], [%1], 16;" :: "r"(dst), "l"(src));
}
__device__ __forceinline__ void mma_bf16(float* c, const uint32_t* a,
                                         uint32_t b0, uint32_t b1) {
    asm volatile(
        "mma.sync.aligned.m16n8k16.row.col.f32.bf16.bf16.f32 "
        "{%0,%1,%2,%3}, {%4,%5,%6,%7}, {%8,%9}, {%0,%1,%2,%3};\n"
        : "+f"(c[0]), "+f"(c[1]), "+f"(c[2]), "+f"(c[3])
        : "r"(a[0]), "r"(a[1]), "r"(a[2]), "r"(a[3]), "r"(b0), "r"(b1));
}

// ---------------------------------------------------------------------------
// Fused weight prep: ALL layers/matrices in ONE launch.
// 27648 blocks; each transposes one 32x32 tile W[K][N] -> WT[N][K] bf16 hi/lo.
// Per layer: tiles [0,2304) = Wq/Wk/Wv/Wo (576 each), [2304,4608) = W1,
// [4608,6912) = W2.
// ---------------------------------------------------------------------------
__global__ void wprep_all(const float* __restrict__ Wq, const float* __restrict__ Wk,
                          const float* __restrict__ Wv, const float* __restrict__ Wo,
                          const float* __restrict__ W1, const float* __restrict__ W2,
                          __nv_bfloat16* __restrict__ wth,
                          __nv_bfloat16* __restrict__ wtl) {
    __shared__ float tile[32][33];
    const size_t DD = (size_t)Dd * Dd, DF = (size_t)Dd * Ff;
    int bidx  = blockIdx.x;
    int layer = bidx / 6912;
    int r     = bidx - layer * 6912;

    const float* W;
    int K, N, n0, k0;
    size_t ofs;
    if (r < 2304) {
        int type = r / 576, t = r - type * 576;
        K = Dd; N = Dd;
        n0 = (t % 24) * 32; k0 = (t / 24) * 32;
        W = ((type == 0) ? Wq : (type == 1) ? Wk : (type == 2) ? Wv : Wo)
            + (size_t)layer * DD;
        ofs = (size_t)(type * 4 + layer) * DD;
    } else if (r < 4608) {
        int t = r - 2304;
        K = Dd; N = Ff;
        n0 = (t % 96) * 32; k0 = (t / 96) * 32;
        W = W1 + (size_t)layer * DF;
        ofs = 16 * DD + (size_t)layer * DF;
    } else {
        int t = r - 4608;
        K = Ff; N = Dd;
        n0 = (t % 24) * 32; k0 = (t / 24) * 32;
        W = W2 + (size_t)layer * DF;
        ofs = 16 * DD + 4 * DF + (size_t)layer * DF;
    }

    int tx = threadIdx.x, ty = threadIdx.y;   // (32, 8)
#pragma unroll
    for (int rr = 0; rr < 32; rr += 8)
        tile[ty + rr][tx] = W[(size_t)(k0 + ty + rr) * N + n0 + tx];
    __syncthreads();
#pragma unroll
    for (int rr = 0; rr < 32; rr += 8) {
        float x = tile[tx][ty + rr];
        __nv_bfloat16 hi, lo;
        split1(x, hi, lo);
        size_t o = ofs + (size_t)(n0 + ty + rr) * K + k0 + tx;
        wth[o] = hi;
        wtl[o] = lo;
    }
}

// ---------------------------------------------------------------------------
// Embedding (emits fp32 + bf16 hi/lo)
// ---------------------------------------------------------------------------
__global__ void embed_kernel(const int* __restrict__ ids,
                             const float* __restrict__ wemb,
                             float* __restrict__ h,
                             __nv_bfloat16* __restrict__ hh,
                             __nv_bfloat16* __restrict__ hl) {
    int idx = blockIdx.x * blockDim.x + threadIdx.x;
    int d   = idx % Dd;
    int row = idx / Dd;
    int l   = row % Ll;
    int j   = d >> 1;
    float ang = (float)l * expf(-9.210340371976184f * (float)(2 * j) / (float)Dd);
    float pe  = (d & 1) ? cosf(ang) : sinf(ang);
    float val = wemb[(size_t)ids[row] * Dd + d] + pe;
    h[idx] = val;
    split1(val, hh[idx], hl[idx]);
}

// ---------------------------------------------------------------------------
// bf16 split-3 GEMM, fused-segment k-chunks, 2-stage pipeline, 2 blocks/SM.
// Per 32-k chunk stage {Ahi, Alo, Bhi, Blo} (40KB), ldsm each fragment once,
// 3 MMA combos: c += ahi*bhi + alo*bhi + ahi*blo.
// BM=BN=128, 256 thr, 8 warps (2x4), warp 64x32 via 4x4 m16n8k16.
// 2 stages x 40KB = 80KB dynamic smem -> 2 co-resident blocks hide latency.
// MODE 0: fp32 out.  MODE 1: ReLU + bf16 hi/lo out.
// ---------------------------------------------------------------------------
#define NSTG  2
#define TILB  10240                    // one 128x32 bf16 tile @ 80B stride
#define STGB  (4 * TILB)               // Ahi|Alo|Bhi|Blo
#define GSMEM (NSTG * STGB)            // 80 KB

template<int MODE>
__device__ __forceinline__ void gemm_tc_core(
        const __nv_bfloat16* __restrict__ Ahi, const __nv_bfloat16* __restrict__ Alo,
        const __nv_bfloat16* __restrict__ Bhi, const __nv_bfloat16* __restrict__ Blo,
        const float* __restrict__ bias, float* __restrict__ C,
        __nv_bfloat16* __restrict__ Chi, __nv_bfloat16* __restrict__ Clo,
        int N, int K, int bm, int bn) {
    extern __shared__ uint8_t dynsmem[];
    uint32_t sbase = (uint32_t)__cvta_generic_to_shared(dynsmem);

    int tid  = threadIdx.x;
    int lane = tid & 31, wid = tid >> 5;
    int wm = wid >> 2, wn = wid & 3;

    const int NCH = K / 32;

    float c[4][4][4];
#pragma unroll
    for (int mt = 0; mt < 4; mt++)
#pragma unroll
        for (int nt = 0; nt < 4; nt++)
#pragma unroll
            for (int r = 0; r < 4; r++) c[mt][nt][r] = 0.0f;

    // Fill stage ch&1 with the 4 tiles of chunk ch (always commits a group).
    auto fill = [&](int ch) {
        if (ch < NCH) {
            int st = ch & (NSTG - 1);
            int kc = ch * 32;
            uint32_t sA = sbase + st * STGB;
#pragma unroll
            for (int i = 0; i < 8; i++) {
                int tile   = i >> 1;                    // constant per i
                int within = (i & 1) * 256 + tid;       // 0..511
                int row = within >> 2, qq = within & 3;
                const __nv_bfloat16* src =
                    (tile == 0) ? Ahi : (tile == 1) ? Alo :
                    (tile == 2) ? Bhi : Blo;
                int grow = ((tile < 2) ? bm : bn) + row;
                cpasync16(sA + tile * TILB + row * 80 + qq * 16,
                          src + (size_t)grow * K + kc + qq * 8);
            }
        }
        asm volatile("cp.async.commit_group;" ::: "memory");
    };

    fill(0); fill(1);

    uint32_t arow = (wm * 64 + (lane & 15)) * 80 + ((lane & 16) ? 16 : 0);
    uint32_t brow = (wn * 32 + (lane & 15)) * 80 + ((lane & 16) ? 16 : 0);

    for (int it = 0; it < NCH; it++) {
        asm volatile("cp.async.wait_group 1;" ::: "memory");
        __syncthreads();

        uint32_t sA = sbase + (it & (NSTG - 1)) * STGB;
#pragma unroll
        for (int ks = 0; ks < 2; ks++) {
            uint32_t ah[4][4], al[4][4], bh[2][4], bl[2][4];
#pragma unroll
            for (int mt = 0; mt < 4; mt++) {
                ldsm_x4(ah[mt], sA + arow + mt * 16 * 80 + ks * 32);
                ldsm_x4(al[mt], sA + TILB + arow + mt * 16 * 80 + ks * 32);
            }
#pragma unroll
            for (int p = 0; p < 2; p++) {
                ldsm_x4(bh[p], sA + 2 * TILB + brow + p * 16 * 80 + ks * 32);
                ldsm_x4(bl[p], sA + 3 * TILB + brow + p * 16 * 80 + ks * 32);
            }
#pragma unroll
            for (int mt = 0; mt < 4; mt++)
#pragma unroll
                for (int nt = 0; nt < 4; nt++) {
                    uint32_t h0 = bh[nt >> 1][nt & 1], h1 = bh[nt >> 1][(nt & 1) + 2];
                    uint32_t l0 = bl[nt >> 1][nt & 1], l1 = bl[nt >> 1][(nt & 1) + 2];
                    mma_bf16(c[mt][nt], ah[mt], h0, h1);
                    mma_bf16(c[mt][nt], al[mt], h0, h1);
                    mma_bf16(c[mt][nt], ah[mt], l0, l1);
                }
        }
        __syncthreads();      // all warps done reading stage it
        fill(it + 2);         // overwrite stage it&1
    }
    asm volatile("cp.async.wait_group 0;" ::: "memory");

    // Epilogue
    int g = lane >> 2, tg = lane & 3;
#pragma unroll
    for (int mt = 0; mt < 4; mt++) {
        int row = bm + wm * 64 + mt * 16 + g;
#pragma unroll
        for (int nt = 0; nt < 4; nt++) {
            int col = bn + wn * 32 + nt * 8 + 2 * tg;
            float b0 = bias[col], b1 = bias[col + 1];
            float v0 = c[mt][nt][0] + b0, v1 = c[mt][nt][1] + b1;
            float v2 = c[mt][nt][2] + b0, v3 = c[mt][nt][3] + b1;
            if (MODE == 1) {
                v0 = fmaxf(v0, 0.f); v1 = fmaxf(v1, 0.f);
                v2 = fmaxf(v2, 0.f); v3 = fmaxf(v3, 0.f);
                __nv_bfloat16 h0, l0, h1, l1, h2, l2, h3, l3;
                split1(v0, h0, l0); split1(v1, h1, l1);
                split1(v2, h2, l2); split1(v3, h3, l3);
                *(__nv_bfloat162*)(Chi + (size_t)row * N + col) =
                    __halves2bfloat162(h0, h1);
                *(__nv_bfloat162*)(Clo + (size_t)row * N + col) =
                    __halves2bfloat162(l0, l1);
                *(__nv_bfloat162*)(Chi + (size_t)(row + 8) * N + col) =
                    __halves2bfloat162(h2, h3);
                *(__nv_bfloat162*)(Clo + (size_t)(row + 8) * N + col) =
                    __halves2bfloat162(l2, l3);
            } else {
                float2 p0 = {v0, v1}, p1 = {v2, v3};
                *(float2*)&C[(size_t)row * N + col]       = p0;
                *(float2*)&C[(size_t)(row + 8) * N + col] = p1;
            }
        }
    }
}

template<int MODE>
__global__ void __launch_bounds__(256, 2) gemm_tc(
        const __nv_bfloat16* Ahi, const __nv_bfloat16* Alo,
        const __nv_bfloat16* Bhi, const __nv_bfloat16* Blo,
        const float* bias, float* C, __nv_bfloat16* Chi, __nv_bfloat16* Clo,
        int N, int K) {
    gemm_tc_core<MODE>(Ahi, Alo, Bhi, Blo, bias, C, Chi, Clo, N, K,
                       blockIdx.y * 128, blockIdx.x * 128);
}

__global__ void __launch_bounds__(256, 2) gemm_qkv(
        const __nv_bfloat16* Ahi, const __nv_bfloat16* Alo,
        const __nv_bfloat16* wth, const __nv_bfloat16* wtl, int l,
        const float* bq, const float* bk, const float* bv,
        float* oq, float* ok, float* ov) {
    int z = blockIdx.z;
    size_t ofs = (size_t)(4 * z + l) * Dd * Dd;
    const float* bb = (z == 0) ? bq : (z == 1) ? bk : bv;
    float*       O  = (z == 0) ? oq : (z == 1) ? ok : ov;
    gemm_tc_core<0>(Ahi, Alo, wth + ofs, wtl + ofs, bb, O, nullptr, nullptr,
                    Dd, Dd, blockIdx.y * 128, blockIdx.x * 128);
}

// ---------------------------------------------------------------------------
// qe[row, h, e] = q[row, h*64:] . edge_emb[e, :]  — 4 rows/block, float4 loads
// ---------------------------------------------------------------------------
__global__ void qe_kernel(const float* __restrict__ q,
                          const float* __restrict__ ee,
                          float* __restrict__ qe) {
    int row0 = blockIdx.x * 4;
    int tid  = threadIdx.x;
    __shared__ float qsh[4 * Dd];
    __shared__ float eesh[Ee * HDd];
    const float4* qsrc = (const float4*)(q + (size_t)row0 * Dd);
    for (int i = tid; i < 4 * Dd / 4; i += 256) ((float4*)qsh)[i] = qsrc[i];
    for (int i = tid; i < Ee * HDd / 4; i += 256)
        ((float4*)eesh)[i] = ((const float4*)ee)[i];
    __syncthreads();
    for (int o = tid; o < 4 * Hh * Ee; o += 256) {
        int r = o / (Hh * Ee), x = o - r * (Hh * Ee);
        int hh = x / Ee, e = x - hh * Ee;
        float s = 0.0f;
#pragma unroll
        for (int d = 0; d < HDd; d++)
            s += qsh[r * Dd + hh * HDd + d] * eesh[e * HDd + d];
        qe[(size_t)(row0 + r) * (Hh * Ee) + x] = s;
    }
}

// ---------------------------------------------------------------------------
// Warp-tiled fused attention (unchanged); epilogue emits bf16 hi/lo.
// ---------------------------------------------------------------------------
#define ATTN_SMEM_BYTES ((256*65 + 256*64 + 8*2048 + 8*416) * 4)

__global__ void __launch_bounds__(256) attn_kernel(
        const float* __restrict__ q, const float* __restrict__ k,
        const float* __restrict__ v, const float* __restrict__ qe,
        const int* __restrict__ et, const int* __restrict__ adj,
        __nv_bfloat16* __restrict__ outh, __nv_bfloat16* __restrict__ outl) {
    int bh = blockIdx.x;
    int b = bh / Hh, h = bh % Hh;
    int tid = threadIdx.x, lane = tid & 31, wid = tid >> 5;

    extern __shared__ float sm[];
    float* Ksh  = sm;
    float* Vsh  = Ksh + 256 * 65;
    float* attw = Vsh + 256 * 64 + wid * 2048;
    float* qew  = Vsh + 256 * 64 + 8 * 2048 + wid * 416;

    for (int idx = tid; idx < 256 * 64; idx += 256) {
        int j = idx >> 6, d = idx & 63;
        size_t gg = (size_t)(b * Ll + j) * Dd + h * HDd + d;
        Ksh[j * 65 + d] = k[gg];
        Vsh[j * 64 + d] = v[gg];
    }
    __syncthreads();

    for (int pass = 0; pass < 4; pass++) {
        int qi0 = pass * 64 + wid * 8;

        float qreg[16];
        {
            const float* qp = q + (size_t)(b * Ll + qi0 + (lane & 7)) * Dd
                                + h * HDd + (lane >> 3) * 16;
#pragma unroll
            for (int r = 0; r < 16; r++) qreg[r] = qp[r];
        }
        for (int x = lane; x < 8 * Ee; x += 32) {
            int qi = x / Ee, e = x - qi * Ee;
            qew[qi * 52 + e] = qe[((size_t)(b * Ll + qi0 + qi) * Hh + h) * Ee + e];
        }
        __syncwarp();

        float s[8][8];
#pragma unroll
        for (int qi = 0; qi < 8; qi++)
#pragma unroll
            for (int t = 0; t < 8; t++) s[qi][t] = 0.0f;

        for (int dblk = 0; dblk < 4; dblk++) {
#pragma unroll
            for (int r = 0; r < 16; r++) {
                int d = dblk * 16 + r;
                float kv[8];
#pragma unroll
                for (int t = 0; t < 8; t++) kv[t] = Ksh[(t * 32 + lane) * 65 + d];
#pragma unroll
                for (int qi = 0; qi < 8; qi++) {
                    float qd = __shfl_sync(0xffffffffu, qreg[r], dblk * 8 + qi);
#pragma unroll
                    for (int t = 0; t < 8; t++) s[qi][t] = fmaf(qd, kv[t], s[qi][t]);
                }
            }
        }

        const int* etp = et  + (size_t)(b * Ll + qi0) * Ll;
        const int* adp = adj + (size_t)(b * Ll + qi0) * Ll;
#pragma unroll
        for (int qi = 0; qi < 8; qi++)
#pragma unroll
            for (int t = 0; t < 8; t++) {
                int j = t * 32 + lane;
                float eb = qew[qi * 52 + etp[qi * Ll + j]];
                s[qi][t] = adp[qi * Ll + j] ? (s[qi][t] + eb) * 0.125f : -1e9f;
            }

#pragma unroll
        for (int qi = 0; qi < 8; qi++) {
            float mx = s[qi][0];
#pragma unroll
            for (int t = 1; t < 8; t++) mx = fmaxf(mx, s[qi][t]);
#pragma unroll
            for (int o = 16; o > 0; o >>= 1)
                mx = fmaxf(mx, __shfl_xor_sync(0xffffffffu, mx, o));
            float sum = 0.0f;
#pragma unroll
            for (int t = 0; t < 8; t++) {
                float p = __expf(s[qi][t] - mx);
                s[qi][t] = p;
                sum += p;
            }
#pragma unroll
            for (int o = 16; o > 0; o >>= 1)
                sum += __shfl_xor_sync(0xffffffffu, sum, o);
            float inv = 1.0f / sum;
#pragma unroll
            for (int t = 0; t < 8; t++) {
                int j = t * 32 + lane;
                attw[j * 8 + ((qi + (j >> 2)) & 7)] = s[qi][t] * inv;
            }
        }
        __syncwarp();

        float o0[8], o1[8];
#pragma unroll
        for (int qi = 0; qi < 8; qi++) { o0[qi] = 0.0f; o1[qi] = 0.0f; }
        for (int j0 = 0; j0 < 256; j0 += 32) {
#pragma unroll
            for (int jj = 0; jj < 32; jj++) {
                int j = j0 + jj;
                float4 A0 = *(const float4*)&attw[j * 8];
                float4 A1 = *(const float4*)&attw[j * 8 + 4];
                float av[8] = {A0.x, A0.y, A0.z, A0.w, A1.x, A1.y, A1.z, A1.w};
                float v0 = Vsh[j * 64 + lane];
                float v1 = Vsh[j * 64 + lane + 32];
#pragma unroll
                for (int qi = 0; qi < 8; qi++) {
                    float a = av[(qi + ((jj >> 2) & 7)) & 7];
                    o0[qi] = fmaf(a, v0, o0[qi]);
                    o1[qi] = fmaf(a, v1, o1[qi]);
                }
            }
        }
#pragma unroll
        for (int qi = 0; qi < 8; qi++) {
            size_t rr = (size_t)(b * Ll + qi0 + qi) * Dd + h * HDd;
            __nv_bfloat16 hi, lo;
            split1(o0[qi], hi, lo);
            outh[rr + lane] = hi;  outl[rr + lane] = lo;
            split1(o1[qi], hi, lo);
            outh[rr + lane + 32] = hi;  outl[rr + lane + 32] = lo;
        }
        __syncwarp();
    }
}

// ---------------------------------------------------------------------------
// Residual + LayerNorm, 2 rows per block (warps 0-3 row A, warps 4-7 row B).
// In-place on h; emits bf16 hi/lo of h.
// ---------------------------------------------------------------------------
__global__ void ln_kernel(float* __restrict__ h,
                          const float* __restrict__ delta,
                          const float* __restrict__ g,
                          const float* __restrict__ beta,
                          __nv_bfloat16* __restrict__ hh,
                          __nv_bfloat16* __restrict__ hl) {
    int grp = threadIdx.x >> 7;             // 0 or 1
    int t   = threadIdx.x & 127;            // 0..127
    int row = blockIdx.x * 2 + grp;
    __shared__ float s1[2][4], s2[2][4], mv[2][2];
    size_t base = (size_t)row * Dd;

    float x[6];
#pragma unroll
    for (int i = 0; i < 6; i++)
        x[i] = h[base + t + i * 128] + delta[base + t + i * 128];

    float s = 0.0f, ss = 0.0f;
#pragma unroll
    for (int i = 0; i < 6; i++) { s += x[i]; ss += x[i] * x[i]; }
#pragma unroll
    for (int o = 16; o > 0; o >>= 1) {
        s  += __shfl_xor_sync(0xffffffffu, s, o);
        ss += __shfl_xor_sync(0xffffffffu, ss, o);
    }
    int lane = t & 31, w4 = t >> 5;          // warp within group (0..3)
    if (lane == 0) { s1[grp][w4] = s; s2[grp][w4] = ss; }
    __syncthreads();
    if (t == 0) {
        float S = s1[grp][0] + s1[grp][1] + s1[grp][2] + s1[grp][3];
        float SS = s2[grp][0] + s2[grp][1] + s2[grp][2] + s2[grp][3];
        float mean = S / (float)Dd;
        mv[grp][0] = mean;
        mv[grp][1] = rsqrtf(SS / (float)Dd - mean * mean + 1e-5f);
    }
    __syncthreads();
    float mean = mv[grp][0], inv = mv[grp][1];
#pragma unroll
    for (int i = 0; i < 6; i++) {
        int d = t + i * 128;
        float y = (x[i] - mean) * inv * g[d] + beta[d];
        h[base + d] = y;
        split1(y, hh[base + d], hl[base + d]);
    }
}

// ---------------------------------------------------------------------------
__global__ void cls_kernel(const float* __restrict__ h,
                           const float* __restrict__ W,
                           const float* __restrict__ bias,
                           float* __restrict__ out) {
    int w    = threadIdx.x >> 5;
    int lane = threadIdx.x & 31;
    for (int o = w * 4; o < w * 4 + 4; o++) {
        int b = o >> 1, c = o & 1;
        float s = 0.0f;
        for (int d = lane; d < Dd; d += 32)
            s += h[(size_t)(b * Ll) * Dd + d] * W[(size_t)d * Cc + c];
#pragma unroll
        for (int off = 16; off > 0; off >>= 1) s += __shfl_xor_sync(0xffffffffu, s, off);
        if (lane == 0) out[o] = s + bias[c];
    }
}

// ---------------------------------------------------------------------------
extern "C" void kernel_launch(void* const* d_in, const int* in_sizes, int n_in,
                              void* d_out, int out_size) {
    const int*   word_ids = (const int*)d_in[0];
    const int*   adj      = (const int*)d_in[1];   // bool -> int32 (harness)
    const int*   et       = (const int*)d_in[2];
    const float* wemb     = (const float*)d_in[3];
    const float* eemb     = (const float*)d_in[4];
    const float* Wq   = (const float*)d_in[5];
    const float* bq   = (const float*)d_in[6];
    const float* Wk   = (const float*)d_in[7];
    const float* bk   = (const float*)d_in[8];
    const float* Wv   = (const float*)d_in[9];
    const float* bv   = (const float*)d_in[10];
    const float* Wo   = (const float*)d_in[11];
    const float* bo   = (const float*)d_in[12];
    const float* ln1g = (const float*)d_in[13];
    const float* ln1b = (const float*)d_in[14];
    const float* W1   = (const float*)d_in[15];
    const float* b1   = (const float*)d_in[16];
    const float* W2   = (const float*)d_in[17];
    const float* b2   = (const float*)d_in[18];
    const float* ln2g = (const float*)d_in[19];
    const float* ln2b = (const float*)d_in[20];
    const float* clsW = (const float*)d_in[21];
    const float* clsb = (const float*)d_in[22];

    float *h, *q, *k, *v, *t, *qe;
    __nv_bfloat16 *hh, *hl, *aoh, *aol, *ffh, *ffl, *wth, *wtl;
    cudaGetSymbolAddress((void**)&h,   g_h);
    cudaGetSymbolAddress((void**)&q,   g_q);
    cudaGetSymbolAddress((void**)&k,   g_k);
    cudaGetSymbolAddress((void**)&v,   g_v);
    cudaGetSymbolAddress((void**)&t,   g_t);
    cudaGetSymbolAddress((void**)&qe,  g_qe);
    cudaGetSymbolAddress((void**)&hh,  g_hh);
    cudaGetSymbolAddress((void**)&hl,  g_hl);
    cudaGetSymbolAddress((void**)&aoh, g_aoh);
    cudaGetSymbolAddress((void**)&aol, g_aol);
    cudaGetSymbolAddress((void**)&ffh, g_ffh);
    cudaGetSymbolAddress((void**)&ffl, g_ffl);
    cudaGetSymbolAddress((void**)&wth, g_wth);
    cudaGetSymbolAddress((void**)&wtl, g_wtl);

    cudaFuncSetAttribute(attn_kernel,
                         cudaFuncAttributeMaxDynamicSharedMemorySize,
                         ATTN_SMEM_BYTES);
    cudaFuncSetAttribute(gemm_tc<0>,
                         cudaFuncAttributeMaxDynamicSharedMemorySize, GSMEM);
    cudaFuncSetAttribute(gemm_tc<1>,
                         cudaFuncAttributeMaxDynamicSharedMemorySize, GSMEM);
    cudaFuncSetAttribute(gemm_qkv,
                         cudaFuncAttributeMaxDynamicSharedMemorySize, GSMEM);

    const size_t DD = (size_t)Dd * Dd, DF = (size_t)Dd * Ff;

    // --- Weight prep: one fused launch for all layers/matrices ---
    wprep_all<<<NLl * 6912, dim3(32, 8)>>>(Wq, Wk, Wv, Wo, W1, W2, wth, wtl);

    embed_kernel<<<ROWS * Dd / 256, 256>>>(word_ids, wemb, h, hh, hl);

    dim3 gQKV(Dd / 128, ROWS / 128, 3);   // (6, 32, 3)
    dim3 gD(Dd / 128, ROWS / 128);        // (6, 32)
    dim3 gF(Ff / 128, ROWS / 128);        // (24, 32)

    for (int l = 0; l < NLl; l++) {
        gemm_qkv<<<gQKV, 256, GSMEM>>>(hh, hl, wth, wtl, l, bq + l * Dd,
                                       bk + l * Dd, bv + l * Dd, q, k, v);

        qe_kernel<<<ROWS / 4, 256>>>(q, eemb, qe);
        attn_kernel<<<Bb * Hh, 256, ATTN_SMEM_BYTES>>>(q, k, v, qe, et, adj,
                                                       aoh, aol);

        gemm_tc<0><<<gD, 256, GSMEM>>>(aoh, aol, wth + 12 * DD + l * DD,
                                       wtl + 12 * DD + l * DD, bo + l * Dd,
                                       t, nullptr, nullptr, Dd, Dd);
        ln_kernel<<<ROWS / 2, 256>>>(h, t, ln1g + l * Dd, ln1b + l * Dd, hh, hl);

        gemm_tc<1><<<gF, 256, GSMEM>>>(hh, hl, wth + 16 * DD + l * DF,
                                       wtl + 16 * DD + l * DF, b1 + l * Ff,
                                       nullptr, ffh, ffl, Ff, Dd);
        gemm_tc<0><<<gD, 256, GSMEM>>>(ffh, ffl, wth + 16 * DD + 4 * DF + l * DF,
                                       wtl + 16 * DD + 4 * DF + l * DF,
                                       b2 + l * Dd, t, nullptr, nullptr, Dd, Ff);
        ln_kernel<<<ROWS / 2, 256>>>(h, t, ln2g + l * Dd, ln2b + l * Dd, hh, hl);
    }

    cls_kernel<<<1, 256>>>(h, clsW, clsb, (float*)d_out);
}

// round 17
// speedup vs baseline: 1.6106x; 1.6106x over previous
#include <cuda_runtime.h>
#include <cuda_bf16.h>
#include <math.h>
#include <stdint.h>

#define Bb   16
#define Ll   256
#define Dd   768
#define Hh   12
#define HDd  64
#define NLl  4
#define Ff   3072
#define Ee   50
#define Cc   2
#define ROWS (Bb * Ll)
#define WTOT (16 * Dd * Dd + 8 * Dd * Ff)

// ---------------------------------------------------------------------------
// Scratch (device globals; no allocations allowed)
// ---------------------------------------------------------------------------
__device__ float g_h [ROWS * Dd];
__device__ float g_q [ROWS * Dd];
__device__ float g_k [ROWS * Dd];
__device__ float g_v [ROWS * Dd];
__device__ float g_t [ROWS * Dd];
__device__ float g_qe[ROWS * Hh * Ee];
__device__ __nv_bfloat16 g_hh [ROWS * Dd], g_hl [ROWS * Dd];
__device__ __nv_bfloat16 g_aoh[ROWS * Dd], g_aol[ROWS * Dd];
__device__ __nv_bfloat16 g_ffh[ROWS * Ff], g_ffl[ROWS * Ff];
__device__ __nv_bfloat16 g_wth[WTOT],      g_wtl[WTOT];

__device__ __forceinline__ void split1(float x, __nv_bfloat16& hi, __nv_bfloat16& lo) {
    hi = __float2bfloat16(x);
    lo = __float2bfloat16(x - __bfloat162float(hi));
}

// ---------------------------------------------------------------------------
// PTX helpers (mma.sync path only — tcgen05 unavailable at compute_103 PTX)
// ---------------------------------------------------------------------------
__device__ __forceinline__ void ldsm_x4(uint32_t* r, uint32_t a) {
    asm volatile("ldmatrix.sync.aligned.m8n8.x4.shared.b16 {%0,%1,%2,%3}, [%4];"
                 : "=r"(r[0]), "=r"(r[1]), "=r"(r[2]), "=r"(r[3]) : "r"(a));
}
__device__ __forceinline__ void cpasync16(uint32_t dst, const void* src) {
    asm volatile("cp.async.cg.shared.global [%0], [%1], 16;" :: "r"(dst), "l"(src));
}
__device__ __forceinline__ void mma_bf16(float* c, const uint32_t* a,
                                         uint32_t b0, uint32_t b1) {
    asm volatile(
        "mma.sync.aligned.m16n8k16.row.col.f32.bf16.bf16.f32 "
        "{%0,%1,%2,%3}, {%4,%5,%6,%7}, {%8,%9}, {%0,%1,%2,%3};\n"
        : "+f"(c[0]), "+f"(c[1]), "+f"(c[2]), "+f"(c[3])
        : "r"(a[0]), "r"(a[1]), "r"(a[2]), "r"(a[3]), "r"(b0), "r"(b1));
}

// ---------------------------------------------------------------------------
// Fused weight prep: ALL layers/matrices in ONE launch.
// 27648 blocks; each transposes one 32x32 tile W[K][N] -> WT[N][K] bf16 hi/lo.
// ---------------------------------------------------------------------------
__global__ void wprep_all(const float* __restrict__ Wq, const float* __restrict__ Wk,
                          const float* __restrict__ Wv, const float* __restrict__ Wo,
                          const float* __restrict__ W1, const float* __restrict__ W2,
                          __nv_bfloat16* __restrict__ wth,
                          __nv_bfloat16* __restrict__ wtl) {
    __shared__ float tile[32][33];
    const size_t DD = (size_t)Dd * Dd, DF = (size_t)Dd * Ff;
    int bidx  = blockIdx.x;
    int layer = bidx / 6912;
    int r     = bidx - layer * 6912;

    const float* W;
    int K, N, n0, k0;
    size_t ofs;
    if (r < 2304) {
        int type = r / 576, t = r - type * 576;
        K = Dd; N = Dd;
        n0 = (t % 24) * 32; k0 = (t / 24) * 32;
        W = ((type == 0) ? Wq : (type == 1) ? Wk : (type == 2) ? Wv : Wo)
            + (size_t)layer * DD;
        ofs = (size_t)(type * 4 + layer) * DD;
    } else if (r < 4608) {
        int t = r - 2304;
        K = Dd; N = Ff;
        n0 = (t % 96) * 32; k0 = (t / 96) * 32;
        W = W1 + (size_t)layer * DF;
        ofs = 16 * DD + (size_t)layer * DF;
    } else {
        int t = r - 4608;
        K = Ff; N = Dd;
        n0 = (t % 24) * 32; k0 = (t / 24) * 32;
        W = W2 + (size_t)layer * DF;
        ofs = 16 * DD + 4 * DF + (size_t)layer * DF;
    }

    int tx = threadIdx.x, ty = threadIdx.y;   // (32, 8)
#pragma unroll
    for (int rr = 0; rr < 32; rr += 8)
        tile[ty + rr][tx] = W[(size_t)(k0 + ty + rr) * N + n0 + tx];
    __syncthreads();
#pragma unroll
    for (int rr = 0; rr < 32; rr += 8) {
        float x = tile[tx][ty + rr];
        __nv_bfloat16 hi, lo;
        split1(x, hi, lo);
        size_t o = ofs + (size_t)(n0 + ty + rr) * K + k0 + tx;
        wth[o] = hi;
        wtl[o] = lo;
    }
}

// ---------------------------------------------------------------------------
// Embedding (emits fp32 + bf16 hi/lo)
// ---------------------------------------------------------------------------
__global__ void embed_kernel(const int* __restrict__ ids,
                             const float* __restrict__ wemb,
                             float* __restrict__ h,
                             __nv_bfloat16* __restrict__ hh,
                             __nv_bfloat16* __restrict__ hl) {
    int idx = blockIdx.x * blockDim.x + threadIdx.x;
    int d   = idx % Dd;
    int row = idx / Dd;
    int l   = row % Ll;
    int j   = d >> 1;
    float ang = (float)l * expf(-9.210340371976184f * (float)(2 * j) / (float)Dd);
    float pe  = (d & 1) ? cosf(ang) : sinf(ang);
    float val = wemb[(size_t)ids[row] * Dd + d] + pe;
    h[idx] = val;
    split1(val, hh[idx], hl[idx]);
}

// ---------------------------------------------------------------------------
// bf16 split-3 GEMM, fused-segment k-chunks (round-15 measured-best config).
// Per 32-k chunk stage {Ahi, Alo, Bhi, Blo} (40KB), ldsm each fragment once,
// 3 MMA combos: c += ahi*bhi + alo*bhi + ahi*blo.
// BM=BN=128, 256 thr, 8 warps (2x4), warp 64x32 via 4x4 m16n8k16.
// 4 stages x 40KB = 160KB dynamic smem, 1 block/SM, 3-chunk prefetch.
// MODE 0: fp32 out.  MODE 1: ReLU + bf16 hi/lo out.
// ---------------------------------------------------------------------------
#define NSTG  4
#define TILB  10240                    // one 128x32 bf16 tile @ 80B stride
#define STGB  (4 * TILB)               // Ahi|Alo|Bhi|Blo
#define GSMEM (NSTG * STGB)            // 160 KB

template<int MODE>
__device__ __forceinline__ void gemm_tc_core(
        const __nv_bfloat16* __restrict__ Ahi, const __nv_bfloat16* __restrict__ Alo,
        const __nv_bfloat16* __restrict__ Bhi, const __nv_bfloat16* __restrict__ Blo,
        const float* __restrict__ bias, float* __restrict__ C,
        __nv_bfloat16* __restrict__ Chi, __nv_bfloat16* __restrict__ Clo,
        int N, int K, int bm, int bn) {
    extern __shared__ uint8_t dynsmem[];
    uint32_t sbase = (uint32_t)__cvta_generic_to_shared(dynsmem);

    int tid  = threadIdx.x;
    int lane = tid & 31, wid = tid >> 5;
    int wm = wid >> 2, wn = wid & 3;

    const int NCH = K / 32;

    float c[4][4][4];
#pragma unroll
    for (int mt = 0; mt < 4; mt++)
#pragma unroll
        for (int nt = 0; nt < 4; nt++)
#pragma unroll
            for (int r = 0; r < 4; r++) c[mt][nt][r] = 0.0f;

    auto fill = [&](int ch) {
        if (ch < NCH) {
            int st = ch & (NSTG - 1);
            int kc = ch * 32;
            uint32_t sA = sbase + st * STGB;
#pragma unroll
            for (int i = 0; i < 8; i++) {
                int tile   = i >> 1;
                int within = (i & 1) * 256 + tid;
                int row = within >> 2, qq = within & 3;
                const __nv_bfloat16* src =
                    (tile == 0) ? Ahi : (tile == 1) ? Alo :
                    (tile == 2) ? Bhi : Blo;
                int grow = ((tile < 2) ? bm : bn) + row;
                cpasync16(sA + tile * TILB + row * 80 + qq * 16,
                          src + (size_t)grow * K + kc + qq * 8);
            }
        }
        asm volatile("cp.async.commit_group;" ::: "memory");
    };

    fill(0); fill(1); fill(2);

    uint32_t arow = (wm * 64 + (lane & 15)) * 80 + ((lane & 16) ? 16 : 0);
    uint32_t brow = (wn * 32 + (lane & 15)) * 80 + ((lane & 16) ? 16 : 0);

    for (int it = 0; it < NCH; it++) {
        asm volatile("cp.async.wait_group 2;" ::: "memory");
        __syncthreads();
        fill(it + 3);   // overwrites stage consumed at it-1 (safe past barrier)

        uint32_t sA = sbase + (it & (NSTG - 1)) * STGB;
#pragma unroll
        for (int ks = 0; ks < 2; ks++) {
            uint32_t ah[4][4], al[4][4], bh[2][4], bl[2][4];
#pragma unroll
            for (int mt = 0; mt < 4; mt++) {
                ldsm_x4(ah[mt], sA + arow + mt * 16 * 80 + ks * 32);
                ldsm_x4(al[mt], sA + TILB + arow + mt * 16 * 80 + ks * 32);
            }
#pragma unroll
            for (int p = 0; p < 2; p++) {
                ldsm_x4(bh[p], sA + 2 * TILB + brow + p * 16 * 80 + ks * 32);
                ldsm_x4(bl[p], sA + 3 * TILB + brow + p * 16 * 80 + ks * 32);
            }
#pragma unroll
            for (int mt = 0; mt < 4; mt++)
#pragma unroll
                for (int nt = 0; nt < 4; nt++) {
                    uint32_t h0 = bh[nt >> 1][nt & 1], h1 = bh[nt >> 1][(nt & 1) + 2];
                    uint32_t l0 = bl[nt >> 1][nt & 1], l1 = bl[nt >> 1][(nt & 1) + 2];
                    mma_bf16(c[mt][nt], ah[mt], h0, h1);
                    mma_bf16(c[mt][nt], al[mt], h0, h1);
                    mma_bf16(c[mt][nt], ah[mt], l0, l1);
                }
        }
    }
    asm volatile("cp.async.wait_group 0;" ::: "memory");

    // Epilogue
    int g = lane >> 2, tg = lane & 3;
#pragma unroll
    for (int mt = 0; mt < 4; mt++) {
        int row = bm + wm * 64 + mt * 16 + g;
#pragma unroll
        for (int nt = 0; nt < 4; nt++) {
            int col = bn + wn * 32 + nt * 8 + 2 * tg;
            float b0 = bias[col], b1 = bias[col + 1];
            float v0 = c[mt][nt][0] + b0, v1 = c[mt][nt][1] + b1;
            float v2 = c[mt][nt][2] + b0, v3 = c[mt][nt][3] + b1;
            if (MODE == 1) {
                v0 = fmaxf(v0, 0.f); v1 = fmaxf(v1, 0.f);
                v2 = fmaxf(v2, 0.f); v3 = fmaxf(v3, 0.f);
                __nv_bfloat16 h0, l0, h1, l1, h2, l2, h3, l3;
                split1(v0, h0, l0); split1(v1, h1, l1);
                split1(v2, h2, l2); split1(v3, h3, l3);
                *(__nv_bfloat162*)(Chi + (size_t)row * N + col) =
                    __halves2bfloat162(h0, h1);
                *(__nv_bfloat162*)(Clo + (size_t)row * N + col) =
                    __halves2bfloat162(l0, l1);
                *(__nv_bfloat162*)(Chi + (size_t)(row + 8) * N + col) =
                    __halves2bfloat162(h2, h3);
                *(__nv_bfloat162*)(Clo + (size_t)(row + 8) * N + col) =
                    __halves2bfloat162(l2, l3);
            } else {
                float2 p0 = {v0, v1}, p1 = {v2, v3};
                *(float2*)&C[(size_t)row * N + col]       = p0;
                *(float2*)&C[(size_t)(row + 8) * N + col] = p1;
            }
        }
    }
}

template<int MODE>
__global__ void __launch_bounds__(256, 1) gemm_tc(
        const __nv_bfloat16* Ahi, const __nv_bfloat16* Alo,
        const __nv_bfloat16* Bhi, const __nv_bfloat16* Blo,
        const float* bias, float* C, __nv_bfloat16* Chi, __nv_bfloat16* Clo,
        int N, int K) {
    gemm_tc_core<MODE>(Ahi, Alo, Bhi, Blo, bias, C, Chi, Clo, N, K,
                       blockIdx.y * 128, blockIdx.x * 128);
}

__global__ void __launch_bounds__(256, 1) gemm_qkv(
        const __nv_bfloat16* Ahi, const __nv_bfloat16* Alo,
        const __nv_bfloat16* wth, const __nv_bfloat16* wtl, int l,
        const float* bq, const float* bk, const float* bv,
        float* oq, float* ok, float* ov) {
    int z = blockIdx.z;
    size_t ofs = (size_t)(4 * z + l) * Dd * Dd;
    const float* bb = (z == 0) ? bq : (z == 1) ? bk : bv;
    float*       O  = (z == 0) ? oq : (z == 1) ? ok : ov;
    gemm_tc_core<0>(Ahi, Alo, wth + ofs, wtl + ofs, bb, O, nullptr, nullptr,
                    Dd, Dd, blockIdx.y * 128, blockIdx.x * 128);
}

// ---------------------------------------------------------------------------
// qe[row, h, e] = q[row, h*64:] . edge_emb[e, :]  — 4 rows/block.
// eesh padded to stride 65: consecutive-e access at fixed d is conflict-free
// (was stride 64 -> 32-way bank conflict -> 240us/launch, issue 6%).
// ---------------------------------------------------------------------------
__global__ void qe_kernel(const float* __restrict__ q,
                          const float* __restrict__ ee,
                          float* __restrict__ qe) {
    int row0 = blockIdx.x * 4;
    int tid  = threadIdx.x;
    __shared__ float qsh[4 * Dd];
    __shared__ float eesh[Ee * 65];
    const float4* qsrc = (const float4*)(q + (size_t)row0 * Dd);
    for (int i = tid; i < 4 * Dd / 4; i += 256) ((float4*)qsh)[i] = qsrc[i];
    for (int i = tid; i < Ee * HDd; i += 256)
        eesh[(i >> 6) * 65 + (i & 63)] = ee[i];
    __syncthreads();
    for (int o = tid; o < 4 * Hh * Ee; o += 256) {
        int r = o / (Hh * Ee), x = o - r * (Hh * Ee);
        int hh = x / Ee, e = x - hh * Ee;
        float s = 0.0f;
#pragma unroll
        for (int d = 0; d < HDd; d++)
            s += qsh[r * Dd + hh * HDd + d] * eesh[e * 65 + d];
        qe[(size_t)(row0 + r) * (Hh * Ee) + x] = s;
    }
}

// ---------------------------------------------------------------------------
// Warp-tiled fused attention (unchanged); epilogue emits bf16 hi/lo.
// ---------------------------------------------------------------------------
#define ATTN_SMEM_BYTES ((256*65 + 256*64 + 8*2048 + 8*416) * 4)

__global__ void __launch_bounds__(256) attn_kernel(
        const float* __restrict__ q, const float* __restrict__ k,
        const float* __restrict__ v, const float* __restrict__ qe,
        const int* __restrict__ et, const int* __restrict__ adj,
        __nv_bfloat16* __restrict__ outh, __nv_bfloat16* __restrict__ outl) {
    int bh = blockIdx.x;
    int b = bh / Hh, h = bh % Hh;
    int tid = threadIdx.x, lane = tid & 31, wid = tid >> 5;

    extern __shared__ float sm[];
    float* Ksh  = sm;
    float* Vsh  = Ksh + 256 * 65;
    float* attw = Vsh + 256 * 64 + wid * 2048;
    float* qew  = Vsh + 256 * 64 + 8 * 2048 + wid * 416;

    for (int idx = tid; idx < 256 * 64; idx += 256) {
        int j = idx >> 6, d = idx & 63;
        size_t gg = (size_t)(b * Ll + j) * Dd + h * HDd + d;
        Ksh[j * 65 + d] = k[gg];
        Vsh[j * 64 + d] = v[gg];
    }
    __syncthreads();

    for (int pass = 0; pass < 4; pass++) {
        int qi0 = pass * 64 + wid * 8;

        float qreg[16];
        {
            const float* qp = q + (size_t)(b * Ll + qi0 + (lane & 7)) * Dd
                                + h * HDd + (lane >> 3) * 16;
#pragma unroll
            for (int r = 0; r < 16; r++) qreg[r] = qp[r];
        }
        for (int x = lane; x < 8 * Ee; x += 32) {
            int qi = x / Ee, e = x - qi * Ee;
            qew[qi * 52 + e] = qe[((size_t)(b * Ll + qi0 + qi) * Hh + h) * Ee + e];
        }
        __syncwarp();

        float s[8][8];
#pragma unroll
        for (int qi = 0; qi < 8; qi++)
#pragma unroll
            for (int t = 0; t < 8; t++) s[qi][t] = 0.0f;

        for (int dblk = 0; dblk < 4; dblk++) {
#pragma unroll
            for (int r = 0; r < 16; r++) {
                int d = dblk * 16 + r;
                float kv[8];
#pragma unroll
                for (int t = 0; t < 8; t++) kv[t] = Ksh[(t * 32 + lane) * 65 + d];
#pragma unroll
                for (int qi = 0; qi < 8; qi++) {
                    float qd = __shfl_sync(0xffffffffu, qreg[r], dblk * 8 + qi);
#pragma unroll
                    for (int t = 0; t < 8; t++) s[qi][t] = fmaf(qd, kv[t], s[qi][t]);
                }
            }
        }

        const int* etp = et  + (size_t)(b * Ll + qi0) * Ll;
        const int* adp = adj + (size_t)(b * Ll + qi0) * Ll;
#pragma unroll
        for (int qi = 0; qi < 8; qi++)
#pragma unroll
            for (int t = 0; t < 8; t++) {
                int j = t * 32 + lane;
                float eb = qew[qi * 52 + etp[qi * Ll + j]];
                s[qi][t] = adp[qi * Ll + j] ? (s[qi][t] + eb) * 0.125f : -1e9f;
            }

#pragma unroll
        for (int qi = 0; qi < 8; qi++) {
            float mx = s[qi][0];
#pragma unroll
            for (int t = 1; t < 8; t++) mx = fmaxf(mx, s[qi][t]);
#pragma unroll
            for (int o = 16; o > 0; o >>= 1)
                mx = fmaxf(mx, __shfl_xor_sync(0xffffffffu, mx, o));
            float sum = 0.0f;
#pragma unroll
            for (int t = 0; t < 8; t++) {
                float p = __expf(s[qi][t] - mx);
                s[qi][t] = p;
                sum += p;
            }
#pragma unroll
            for (int o = 16; o > 0; o >>= 1)
                sum += __shfl_xor_sync(0xffffffffu, sum, o);
            float inv = 1.0f / sum;
#pragma unroll
            for (int t = 0; t < 8; t++) {
                int j = t * 32 + lane;
                attw[j * 8 + ((qi + (j >> 2)) & 7)] = s[qi][t] * inv;
            }
        }
        __syncwarp();

        float o0[8], o1[8];
#pragma unroll
        for (int qi = 0; qi < 8; qi++) { o0[qi] = 0.0f; o1[qi] = 0.0f; }
        for (int j0 = 0; j0 < 256; j0 += 32) {
#pragma unroll
            for (int jj = 0; jj < 32; jj++) {
                int j = j0 + jj;
                float4 A0 = *(const float4*)&attw[j * 8];
                float4 A1 = *(const float4*)&attw[j * 8 + 4];
                float av[8] = {A0.x, A0.y, A0.z, A0.w, A1.x, A1.y, A1.z, A1.w};
                float v0 = Vsh[j * 64 + lane];
                float v1 = Vsh[j * 64 + lane + 32];
#pragma unroll
                for (int qi = 0; qi < 8; qi++) {
                    float a = av[(qi + ((jj >> 2) & 7)) & 7];
                    o0[qi] = fmaf(a, v0, o0[qi]);
                    o1[qi] = fmaf(a, v1, o1[qi]);
                }
            }
        }
#pragma unroll
        for (int qi = 0; qi < 8; qi++) {
            size_t rr = (size_t)(b * Ll + qi0 + qi) * Dd + h * HDd;
            __nv_bfloat16 hi, lo;
            split1(o0[qi], hi, lo);
            outh[rr + lane] = hi;  outl[rr + lane] = lo;
            split1(o1[qi], hi, lo);
            outh[rr + lane + 32] = hi;  outl[rr + lane + 32] = lo;
        }
        __syncwarp();
    }
}

// ---------------------------------------------------------------------------
// Residual + LayerNorm, 2 rows per block. In-place on h; emits bf16 hi/lo.
// ---------------------------------------------------------------------------
__global__ void ln_kernel(float* __restrict__ h,
                          const float* __restrict__ delta,
                          const float* __restrict__ g,
                          const float* __restrict__ beta,
                          __nv_bfloat16* __restrict__ hh,
                          __nv_bfloat16* __restrict__ hl) {
    int grp = threadIdx.x >> 7;             // 0 or 1
    int t   = threadIdx.x & 127;            // 0..127
    int row = blockIdx.x * 2 + grp;
    __shared__ float s1[2][4], s2[2][4], mv[2][2];
    size_t base = (size_t)row * Dd;

    float x[6];
#pragma unroll
    for (int i = 0; i < 6; i++)
        x[i] = h[base + t + i * 128] + delta[base + t + i * 128];

    float s = 0.0f, ss = 0.0f;
#pragma unroll
    for (int i = 0; i < 6; i++) { s += x[i]; ss += x[i] * x[i]; }
#pragma unroll
    for (int o = 16; o > 0; o >>= 1) {
        s  += __shfl_xor_sync(0xffffffffu, s, o);
        ss += __shfl_xor_sync(0xffffffffu, ss, o);
    }
    int lane = t & 31, w4 = t >> 5;
    if (lane == 0) { s1[grp][w4] = s; s2[grp][w4] = ss; }
    __syncthreads();
    if (t == 0) {
        float S  = s1[grp][0] + s1[grp][1] + s1[grp][2] + s1[grp][3];
        float SS = s2[grp][0] + s2[grp][1] + s2[grp][2] + s2[grp][3];
        float mean = S / (float)Dd;
        mv[grp][0] = mean;
        mv[grp][1] = rsqrtf(SS / (float)Dd - mean * mean + 1e-5f);
    }
    __syncthreads();
    float mean = mv[grp][0], inv = mv[grp][1];
#pragma unroll
    for (int i = 0; i < 6; i++) {
        int d = t + i * 128;
        float y = (x[i] - mean) * inv * g[d] + beta[d];
        h[base + d] = y;
        split1(y, hh[base + d], hl[base + d]);
    }
}

// ---------------------------------------------------------------------------
__global__ void cls_kernel(const float* __restrict__ h,
                           const float* __restrict__ W,
                           const float* __restrict__ bias,
                           float* __restrict__ out) {
    int w    = threadIdx.x >> 5;
    int lane = threadIdx.x & 31;
    for (int o = w * 4; o < w * 4 + 4; o++) {
        int b = o >> 1, c = o & 1;
        float s = 0.0f;
        for (int d = lane; d < Dd; d += 32)
            s += h[(size_t)(b * Ll) * Dd + d] * W[(size_t)d * Cc + c];
#pragma unroll
        for (int off = 16; off > 0; off >>= 1) s += __shfl_xor_sync(0xffffffffu, s, off);
        if (lane == 0) out[o] = s + bias[c];
    }
}

// ---------------------------------------------------------------------------
extern "C" void kernel_launch(void* const* d_in, const int* in_sizes, int n_in,
                              void* d_out, int out_size) {
    const int*   word_ids = (const int*)d_in[0];
    const int*   adj      = (const int*)d_in[1];   // bool -> int32 (harness)
    const int*   et       = (const int*)d_in[2];
    const float* wemb     = (const float*)d_in[3];
    const float* eemb     = (const float*)d_in[4];
    const float* Wq   = (const float*)d_in[5];
    const float* bq   = (const float*)d_in[6];
    const float* Wk   = (const float*)d_in[7];
    const float* bk   = (const float*)d_in[8];
    const float* Wv   = (const float*)d_in[9];
    const float* bv   = (const float*)d_in[10];
    const float* Wo   = (const float*)d_in[11];
    const float* bo   = (const float*)d_in[12];
    const float* ln1g = (const float*)d_in[13];
    const float* ln1b = (const float*)d_in[14];
    const float* W1   = (const float*)d_in[15];
    const float* b1   = (const float*)d_in[16];
    const float* W2   = (const float*)d_in[17];
    const float* b2   = (const float*)d_in[18];
    const float* ln2g = (const float*)d_in[19];
    const float* ln2b = (const float*)d_in[20];
    const float* clsW = (const float*)d_in[21];
    const float* clsb = (const float*)d_in[22];

    float *h, *q, *k, *v, *t, *qe;
    __nv_bfloat16 *hh, *hl, *aoh, *aol, *ffh, *ffl, *wth, *wtl;
    cudaGetSymbolAddress((void**)&h,   g_h);
    cudaGetSymbolAddress((void**)&q,   g_q);
    cudaGetSymbolAddress((void**)&k,   g_k);
    cudaGetSymbolAddress((void**)&v,   g_v);
    cudaGetSymbolAddress((void**)&t,   g_t);
    cudaGetSymbolAddress((void**)&qe,  g_qe);
    cudaGetSymbolAddress((void**)&hh,  g_hh);
    cudaGetSymbolAddress((void**)&hl,  g_hl);
    cudaGetSymbolAddress((void**)&aoh, g_aoh);
    cudaGetSymbolAddress((void**)&aol, g_aol);
    cudaGetSymbolAddress((void**)&ffh, g_ffh);
    cudaGetSymbolAddress((void**)&ffl, g_ffl);
    cudaGetSymbolAddress((void**)&wth, g_wth);
    cudaGetSymbolAddress((void**)&wtl, g_wtl);

    cudaFuncSetAttribute(attn_kernel,
                         cudaFuncAttributeMaxDynamicSharedMemorySize,
                         ATTN_SMEM_BYTES);
    cudaFuncSetAttribute(gemm_tc<0>,
                         cudaFuncAttributeMaxDynamicSharedMemorySize, GSMEM);
    cudaFuncSetAttribute(gemm_tc<1>,
                         cudaFuncAttributeMaxDynamicSharedMemorySize, GSMEM);
    cudaFuncSetAttribute(gemm_qkv,
                         cudaFuncAttributeMaxDynamicSharedMemorySize, GSMEM);

    const size_t DD = (size_t)Dd * Dd, DF = (size_t)Dd * Ff;

    // --- Weight prep: one fused launch for all layers/matrices ---
    wprep_all<<<NLl * 6912, dim3(32, 8)>>>(Wq, Wk, Wv, Wo, W1, W2, wth, wtl);

    embed_kernel<<<ROWS * Dd / 256, 256>>>(word_ids, wemb, h, hh, hl);

    dim3 gQKV(Dd / 128, ROWS / 128, 3);   // (6, 32, 3)
    dim3 gD(Dd / 128, ROWS / 128);        // (6, 32)
    dim3 gF(Ff / 128, ROWS / 128);        // (24, 32)

    for (int l = 0; l < NLl; l++) {
        gemm_qkv<<<gQKV, 256, GSMEM>>>(hh, hl, wth, wtl, l, bq + l * Dd,
                                       bk + l * Dd, bv + l * Dd, q, k, v);

        qe_kernel<<<ROWS / 4, 256>>>(q, eemb, qe);
        attn_kernel<<<Bb * Hh, 256, ATTN_SMEM_BYTES>>>(q, k, v, qe, et, adj,
                                                       aoh, aol);

        gemm_tc<0><<<gD, 256, GSMEM>>>(aoh, aol, wth + 12 * DD + l * DD,
                                       wtl + 12 * DD + l * DD, bo + l * Dd,
                                       t, nullptr, nullptr, Dd, Dd);
        ln_kernel<<<ROWS / 2, 256>>>(h, t, ln1g + l * Dd, ln1b + l * Dd, hh, hl);

        gemm_tc<1><<<gF, 256, GSMEM>>>(hh, hl, wth + 16 * DD + l * DF,
                                       wtl + 16 * DD + l * DF, b1 + l * Ff,
                                       nullptr, ffh, ffl, Ff, Dd);
        gemm_tc<0><<<gD, 256, GSMEM>>>(ffh, ffl, wth + 16 * DD + 4 * DF + l * DF,
                                       wtl + 16 * DD + 4 * DF + l * DF,
                                       b2 + l * Dd, t, nullptr, nullptr, Dd, Ff);
        ln_kernel<<<ROWS / 2, 256>>>(h, t, ln2g + l * Dd, ln2b + l * Dd, hh, hl);
    }

    cls_kernel<<<1, 256>>>(h, clsW, clsb, (float*)d_out);
}